// round 1
// baseline (speedup 1.0000x reference)
#include <cuda_runtime.h>
#include <cuda_bf16.h>
#include <mma.h>
#include <cstdint>

using namespace nvcuda;

// Problem constants
static constexpr int Bb   = 4;
static constexpr int Sseq = 2048;
static constexpr int Eemb = 1024;
static constexpr int Hh   = 16;
static constexpr int Dd   = 64;           // head dim
static constexpr int Mrows = Bb * Sseq;   // 8192

// Scratch (device globals: allocation-free)
__device__ float g_q[(size_t)Mrows * Eemb];
__device__ float g_k[(size_t)Mrows * Eemb];
__device__ float g_v[(size_t)Mrows * Eemb];
__device__ float g_o[(size_t)Mrows * Eemb];

// ---------------------------------------------------------------------------
// GEMM: C[M,N] = A[M,K] @ W[K,N] + bias[N]   (M=8192, K=N=1024), tf32 wmma
// Block tile 128x128x32, 256 threads (8 warps, each 32x64)
// ---------------------------------------------------------------------------
__global__ __launch_bounds__(256) void gemm_bias_kernel(
    const float* __restrict__ A, const float* __restrict__ W,
    const float* __restrict__ bias, float* __restrict__ C)
{
    constexpr int BM = 128, BN = 128, BK = 32;
    constexpr int K = 1024, N = 1024;

    __shared__ float As[BM * BK];          // 16 KB
    __shared__ float Bs[BK * BN];          // 16 KB
    __shared__ float biasT[16 * BN];       // 8 KB (16 identical rows)

    const int tid  = threadIdx.x;
    const int bm   = blockIdx.y * BM;
    const int bn   = blockIdx.x * BN;
    const int warp = tid >> 5;
    const int wr   = warp >> 1;            // 0..3 -> row offset wr*32
    const int wc   = warp & 1;             // 0..1 -> col offset wc*64

    // broadcast bias into a 16-row tile so we can init accumulators from it
    for (int idx = tid; idx < 16 * BN; idx += 256)
        biasT[idx] = bias[bn + (idx & (BN - 1))];
    __syncthreads();

    wmma::fragment<wmma::accumulator, 16, 16, 8, float> acc[2][4];
    #pragma unroll
    for (int i = 0; i < 2; i++)
        #pragma unroll
        for (int j = 0; j < 4; j++)
            wmma::load_matrix_sync(acc[i][j], biasT + wc * 64 + j * 16, BN,
                                   wmma::mem_row_major);
    __syncthreads();

    for (int k0 = 0; k0 < K; k0 += BK) {
        // load A tile: 128x32 = 1024 float4, 256 threads -> 4 each
        #pragma unroll
        for (int t = 0; t < 4; t++) {
            int lin = tid + t * 256;
            int r = lin >> 3, c4 = lin & 7;
            float4 va = *(const float4*)(A + (size_t)(bm + r) * K + k0 + c4 * 4);
            *(float4*)(As + r * BK + c4 * 4) = va;
        }
        // load W tile: 32x128 = 1024 float4
        #pragma unroll
        for (int t = 0; t < 4; t++) {
            int lin = tid + t * 256;
            int r = lin >> 5, c4 = lin & 31;
            float4 vb = *(const float4*)(W + (size_t)(k0 + r) * N + bn + c4 * 4);
            *(float4*)(Bs + r * BN + c4 * 4) = vb;
        }
        __syncthreads();

        #pragma unroll
        for (int kk = 0; kk < BK; kk += 8) {
            wmma::fragment<wmma::matrix_a, 16, 16, 8, wmma::precision::tf32,
                           wmma::row_major> af[2];
            #pragma unroll
            for (int i = 0; i < 2; i++) {
                wmma::load_matrix_sync(af[i], As + (wr * 32 + i * 16) * BK + kk, BK);
                #pragma unroll
                for (int t = 0; t < af[i].num_elements; t++)
                    af[i].x[t] = wmma::__float_to_tf32(af[i].x[t]);
            }
            #pragma unroll
            for (int j = 0; j < 4; j++) {
                wmma::fragment<wmma::matrix_b, 16, 16, 8, wmma::precision::tf32,
                               wmma::row_major> bf;
                wmma::load_matrix_sync(bf, Bs + kk * BN + wc * 64 + j * 16, BN);
                #pragma unroll
                for (int t = 0; t < bf.num_elements; t++)
                    bf.x[t] = wmma::__float_to_tf32(bf.x[t]);
                #pragma unroll
                for (int i = 0; i < 2; i++)
                    wmma::mma_sync(acc[i][j], af[i], bf, acc[i][j]);
            }
        }
        __syncthreads();
    }

    #pragma unroll
    for (int i = 0; i < 2; i++)
        #pragma unroll
        for (int j = 0; j < 4; j++)
            wmma::store_matrix_sync(
                C + (size_t)(bm + wr * 32 + i * 16) * N + bn + wc * 64 + j * 16,
                acc[i][j], N, wmma::mem_row_major);
}

// ---------------------------------------------------------------------------
// Causal flash attention, tf32 wmma.
// Grid: (S/64 q-tiles, B*H). Block: 128 threads (4 warps). Br=Bc=64, D=64.
// ---------------------------------------------------------------------------
static constexpr int LDP = 72;  // padded tile leading dim (floats)
static constexpr int TILE_F = 64 * LDP;
static constexpr int FLASH_SMEM_BYTES = (6 * TILE_F + 3 * 64) * (int)sizeof(float);

__global__ __launch_bounds__(128) void flash_kernel(
    const float* __restrict__ Q, const float* __restrict__ Kg,
    const float* __restrict__ V, float* __restrict__ O)
{
    extern __shared__ float sm[];
    float* Qs = sm;
    float* Ks = Qs + TILE_F;
    float* Vs = Ks + TILE_F;
    float* Ss = Vs + TILE_F;
    float* Ts = Ss + TILE_F;
    float* Os = Ts + TILE_F;
    float* mrow = Os + TILE_F;   // [64]
    float* lrow = mrow + 64;     // [64]
    float* arow = lrow + 64;     // [64]

    const int tid  = threadIdx.x;
    const int warp = tid >> 5;
    const int qt   = blockIdx.x;            // q tile (0..31)
    const int bh   = blockIdx.y;            // 0..63
    const int b    = bh >> 4;
    const int h    = bh & 15;
    const float scale = 0.125f;             // 1/sqrt(64)

    const float* qb = Q + ((size_t)b * Sseq + (size_t)qt * 64) * Eemb + h * Dd;
    const float* kb = Kg + (size_t)b * Sseq * Eemb + h * Dd;
    const float* vb = V + (size_t)b * Sseq * Eemb + h * Dd;

    // load Q tile 64x64 (16 float4 per row), 128 threads x 8 float4
    #pragma unroll
    for (int t = 0; t < 8; t++) {
        int lin = tid + t * 128;
        int r = lin >> 4, c4 = lin & 15;
        float4 v4 = *(const float4*)(qb + (size_t)r * Eemb + c4 * 4);
        *(float4*)(Qs + r * LDP + c4 * 4) = v4;
    }
    if (tid < 64) { mrow[tid] = -1e30f; lrow[tid] = 0.f; }
    for (int idx = tid; idx < 64 * 64; idx += 128) {
        int r = idx >> 6, c = idx & 63;
        Os[r * LDP + c] = 0.f;
    }
    __syncthreads();

    for (int j = 0; j <= qt; j++) {
        // load K,V tiles for key block j
        const float* kt = kb + (size_t)j * 64 * Eemb;
        const float* vt = vb + (size_t)j * 64 * Eemb;
        #pragma unroll
        for (int t = 0; t < 8; t++) {
            int lin = tid + t * 128;
            int r = lin >> 4, c4 = lin & 15;
            *(float4*)(Ks + r * LDP + c4 * 4) =
                *(const float4*)(kt + (size_t)r * Eemb + c4 * 4);
            *(float4*)(Vs + r * LDP + c4 * 4) =
                *(const float4*)(vt + (size_t)r * Eemb + c4 * 4);
        }
        __syncthreads();

        // S = Q @ K^T  (per-warp: 16 rows x 64 cols)
        {
            wmma::fragment<wmma::accumulator, 16, 16, 8, float> sacc[4];
            #pragma unroll
            for (int n = 0; n < 4; n++) wmma::fill_fragment(sacc[n], 0.f);
            #pragma unroll
            for (int kk = 0; kk < 64; kk += 8) {
                wmma::fragment<wmma::matrix_a, 16, 16, 8, wmma::precision::tf32,
                               wmma::row_major> af;
                wmma::load_matrix_sync(af, Qs + (warp * 16) * LDP + kk, LDP);
                #pragma unroll
                for (int t = 0; t < af.num_elements; t++)
                    af.x[t] = wmma::__float_to_tf32(af.x[t]);
                #pragma unroll
                for (int n = 0; n < 4; n++) {
                    wmma::fragment<wmma::matrix_b, 16, 16, 8, wmma::precision::tf32,
                                   wmma::col_major> bf;
                    wmma::load_matrix_sync(bf, Ks + (n * 16) * LDP + kk, LDP);
                    #pragma unroll
                    for (int t = 0; t < bf.num_elements; t++)
                        bf.x[t] = wmma::__float_to_tf32(bf.x[t]);
                    wmma::mma_sync(sacc[n], af, bf, sacc[n]);
                }
            }
            #pragma unroll
            for (int n = 0; n < 4; n++)
                wmma::store_matrix_sync(Ss + (warp * 16) * LDP + n * 16, sacc[n],
                                        LDP, wmma::mem_row_major);
        }
        __syncthreads();

        // causal mask on diagonal tile
        if (j == qt) {
            for (int idx = tid; idx < 64 * 64; idx += 128) {
                int r = idx >> 6, c = idx & 63;
                if (c > r) Ss[r * LDP + c] = -1e30f;
            }
            __syncthreads();
        }

        // online softmax (thread r owns row r)
        if (tid < 64) {
            int r = tid;
            float mo = mrow[r];
            float mx = mo;
            #pragma unroll 8
            for (int c = 0; c < 64; c++)
                mx = fmaxf(mx, Ss[r * LDP + c] * scale);
            float al = expf(mo - mx);
            float sum = 0.f;
            #pragma unroll 8
            for (int c = 0; c < 64; c++) {
                float p = expf(Ss[r * LDP + c] * scale - mx);
                Ss[r * LDP + c] = p;
                sum += p;
            }
            mrow[r] = mx;
            lrow[r] = lrow[r] * al + sum;
            arow[r] = al;
        }
        __syncthreads();

        // T = P @ V
        {
            wmma::fragment<wmma::accumulator, 16, 16, 8, float> tacc[4];
            #pragma unroll
            for (int n = 0; n < 4; n++) wmma::fill_fragment(tacc[n], 0.f);
            #pragma unroll
            for (int kk = 0; kk < 64; kk += 8) {
                wmma::fragment<wmma::matrix_a, 16, 16, 8, wmma::precision::tf32,
                               wmma::row_major> af;
                wmma::load_matrix_sync(af, Ss + (warp * 16) * LDP + kk, LDP);
                #pragma unroll
                for (int t = 0; t < af.num_elements; t++)
                    af.x[t] = wmma::__float_to_tf32(af.x[t]);
                #pragma unroll
                for (int n = 0; n < 4; n++) {
                    wmma::fragment<wmma::matrix_b, 16, 16, 8, wmma::precision::tf32,
                                   wmma::row_major> bf;
                    wmma::load_matrix_sync(bf, Vs + kk * LDP + n * 16, LDP);
                    #pragma unroll
                    for (int t = 0; t < bf.num_elements; t++)
                        bf.x[t] = wmma::__float_to_tf32(bf.x[t]);
                    wmma::mma_sync(tacc[n], af, bf, tacc[n]);
                }
            }
            #pragma unroll
            for (int n = 0; n < 4; n++)
                wmma::store_matrix_sync(Ts + (warp * 16) * LDP + n * 16, tacc[n],
                                        LDP, wmma::mem_row_major);
        }
        __syncthreads();

        // O = O*alpha + T
        for (int idx = tid; idx < 64 * 64; idx += 128) {
            int r = idx >> 6, c = idx & 63;
            Os[r * LDP + c] = Os[r * LDP + c] * arow[r] + Ts[r * LDP + c];
        }
        __syncthreads();
    }

    // epilogue: write O / l
    float* ob = O + ((size_t)b * Sseq + (size_t)qt * 64) * Eemb + h * Dd;
    for (int idx = tid; idx < 64 * 64; idx += 128) {
        int r = idx >> 6, c = idx & 63;
        ob[(size_t)r * Eemb + c] = Os[r * LDP + c] / lrow[r];
    }
}

// ---------------------------------------------------------------------------
extern "C" void kernel_launch(void* const* d_in, const int* in_sizes, int n_in,
                              void* d_out, int out_size)
{
    const float* q   = (const float*)d_in[0];
    const float* k   = (const float*)d_in[1];
    const float* v   = (const float*)d_in[2];
    const float* w_q = (const float*)d_in[3];
    const float* b_q = (const float*)d_in[4];
    const float* w_k = (const float*)d_in[5];
    const float* b_k = (const float*)d_in[6];
    const float* w_v = (const float*)d_in[7];
    const float* b_v = (const float*)d_in[8];
    const float* w_o = (const float*)d_in[9];
    const float* b_o = (const float*)d_in[10];
    float* out = (float*)d_out;

    float *gq, *gk, *gv, *go;
    cudaGetSymbolAddress((void**)&gq, g_q);
    cudaGetSymbolAddress((void**)&gk, g_k);
    cudaGetSymbolAddress((void**)&gv, g_v);
    cudaGetSymbolAddress((void**)&go, g_o);

    cudaFuncSetAttribute(flash_kernel,
                         cudaFuncAttributeMaxDynamicSharedMemorySize,
                         FLASH_SMEM_BYTES);

    dim3 gGrid(Eemb / 128, Mrows / 128);   // (8, 64)
    gemm_bias_kernel<<<gGrid, 256>>>(q, w_q, b_q, gq);
    gemm_bias_kernel<<<gGrid, 256>>>(k, w_k, b_k, gk);
    gemm_bias_kernel<<<gGrid, 256>>>(v, w_v, b_v, gv);

    dim3 fGrid(Sseq / 64, Bb * Hh);        // (32, 64)
    flash_kernel<<<fGrid, 128, FLASH_SMEM_BYTES>>>(gq, gk, gv, go);

    gemm_bias_kernel<<<gGrid, 256>>>(go, w_o, b_o, out);
}